// round 2
// baseline (speedup 1.0000x reference)
#include <cuda_runtime.h>
#include <cstdint>

// y = spikes @ V @ U^T
// spikes: [512, 32768] f32   (d_in[0])
// U     : [32768, 64]  f32   (d_in[1])
// V     : [32768, 64]  f32   (d_in[2])
// mask_* inputs are unused (reference ignores them).
// out   : [512, 32768] f32

constexpr int BATCH = 512;
constexpr int NPRE  = 32768;
constexpr int NPOST = 32768;
constexpr int R     = 64;

constexpr int KSPLIT = 64;
constexpr int KCHUNK = NPRE / KSPLIT;   // 512

// ---------------- scratch (allocation-free: device globals) ----------------
__device__ float g_Zpart[KSPLIT * BATCH * R];  // 8 MB split-K partials
__device__ float g_Z[BATCH * R];               // 128 KB reduced Z

// ---------------- packed fp32x2 helpers (Blackwell FFMA2) ------------------
__device__ __forceinline__ unsigned long long pack2(float lo, float hi) {
    unsigned long long r;
    asm("mov.b64 %0, {%1, %2};" : "=l"(r) : "f"(lo), "f"(hi));
    return r;
}
__device__ __forceinline__ void unpack2(unsigned long long v, float& lo, float& hi) {
    asm("mov.b64 {%0, %1}, %2;" : "=f"(lo), "=f"(hi) : "l"(v));
}
__device__ __forceinline__ unsigned long long ffma2(unsigned long long a,
                                                    unsigned long long b,
                                                    unsigned long long c) {
    unsigned long long d;
    asm("fma.rn.f32x2 %0, %1, %2, %3;" : "=l"(d) : "l"(a), "l"(b), "l"(c));
    return d;
}

// ===========================================================================
// Kernel A: split-K GEMM1.  Zpart[ks][b][r] = sum_{k in chunk} spikes[b][k]*V[k][r]
// Tile: 128 batch rows x 64 r, K-tile 32.  256 threads, microtile 4(b) x 8(r).
// ===========================================================================
constexpr int A_BM = 128;
constexpr int A_KT = 32;

__global__ void __launch_bounds__(256, 1)
gemm1_kernel(const float* __restrict__ S, const float* __restrict__ V) {
    __shared__ float As[A_BM][40];   // [b][k], row stride 40 floats (160B, 16B-aligned)
    __shared__ float Bs[A_KT][64];   // [k][r]

    const int ks    = blockIdx.x;
    const int btile = blockIdx.y;
    const int tid   = threadIdx.x;
    const int tn = tid & 7;          // 8 col groups
    const int tb = tid >> 3;         // 32 row groups
    const int n0 = tn * 8;
    const int b0 = tb * 4;

    unsigned long long acc[4][4];
#pragma unroll
    for (int i = 0; i < 4; i++)
#pragma unroll
        for (int j = 0; j < 4; j++) acc[i][j] = 0ULL;   // bits of (0.f, 0.f)

    const int kbase = ks * KCHUNK;

    for (int kt = 0; kt < KCHUNK; kt += A_KT) {
        // Load spikes tile: 128 rows x 32 k  (per warp: 4 rows x 128B, coalesced)
#pragma unroll
        for (int l = tid; l < 1024; l += 256) {
            int kg = l & 7, b = l >> 3;
            float4 v = *(const float4*)(S + (size_t)(btile * A_BM + b) * NPRE
                                          + kbase + kt + kg * 4);
            *(float4*)&As[b][kg * 4] = v;
        }
        // Load V tile: 32 k x 64 r (per warp: 2 rows x 256B, coalesced)
#pragma unroll
        for (int l = tid; l < 512; l += 256) {
            int rg = l & 15, kk = l >> 4;
            float4 v = *(const float4*)(V + (size_t)(kbase + kt + kk) * R + rg * 4);
            *(float4*)&Bs[kk][rg * 4] = v;
        }
        __syncthreads();

#pragma unroll 16
        for (int kk = 0; kk < A_KT; kk++) {
            float4 u = *(float4*)&Bs[kk][n0];
            float4 w = *(float4*)&Bs[kk][n0 + 4];
            unsigned long long bb0 = pack2(u.x, u.y);
            unsigned long long bb1 = pack2(u.z, u.w);
            unsigned long long bb2 = pack2(w.x, w.y);
            unsigned long long bb3 = pack2(w.z, w.w);
#pragma unroll
            for (int i = 0; i < 4; i++) {
                float a = As[b0 + i][kk];            // broadcast (4 addrs/warp)
                unsigned long long aa = pack2(a, a);
                acc[i][0] = ffma2(aa, bb0, acc[i][0]);
                acc[i][1] = ffma2(aa, bb1, acc[i][1]);
                acc[i][2] = ffma2(aa, bb2, acc[i][2]);
                acc[i][3] = ffma2(aa, bb3, acc[i][3]);
            }
        }
        __syncthreads();
    }

    // Epilogue: write partials (plain stores; deterministic)
    const int brow = btile * A_BM + b0;
    float* out = g_Zpart + ((size_t)ks * BATCH + brow) * R + n0;
#pragma unroll
    for (int i = 0; i < 4; i++) {
        float4 o0, o1;
        unpack2(acc[i][0], o0.x, o0.y);
        unpack2(acc[i][1], o0.z, o0.w);
        unpack2(acc[i][2], o1.x, o1.y);
        unpack2(acc[i][3], o1.z, o1.w);
        *(float4*)(out + (size_t)i * R)     = o0;
        *(float4*)(out + (size_t)i * R + 4) = o1;
    }
}

// ===========================================================================
// Kernel B: reduce split-K partials.  Z[i] = sum_ks Zpart[ks][i]
// ===========================================================================
__global__ void __launch_bounds__(256, 1)
reduce_z_kernel() {
    const int idx = blockIdx.x * 256 + threadIdx.x;   // 0 .. 32767
    float s = 0.f;
#pragma unroll
    for (int ks = 0; ks < KSPLIT; ks++)
        s += g_Zpart[(size_t)ks * (BATCH * R) + idx];
    g_Z[idx] = s;
}

// ===========================================================================
// Kernel C: GEMM2.  Y[b][n] = sum_r Z[b][r] * U[n][r]
// Tile: 64 batch x 64 post, full K=64 in smem. 128 threads, microtile 4(b) x 8(n).
// ===========================================================================
__global__ void __launch_bounds__(128, 1)
gemm2_kernel(const float* __restrict__ U, float* __restrict__ Y) {
    __shared__ float Zs[64][64];     // [b][r]
    __shared__ float Ut[64][68];     // [r][n], row stride 272B (16B-aligned!)

    const int ntile = blockIdx.x;
    const int btile = blockIdx.y;
    const int tid   = threadIdx.x;
    const int tn = tid & 7;          // 8 col groups
    const int tb = tid >> 3;         // 16 row groups
    const int n0 = tn * 8;
    const int b0 = tb * 4;

    // Load Z tile (64 x 64), direct copy
#pragma unroll
    for (int l = tid; l < 1024; l += 128) {
        int rg = l & 15, b = l >> 4;
        *(float4*)&Zs[b][rg * 4] =
            *(const float4*)(g_Z + (size_t)(btile * 64 + b) * R + rg * 4);
    }
    // Load U tile transposed into Ut[r][n]
#pragma unroll
    for (int l = tid; l < 1024; l += 128) {
        int rg = l & 15, n = l >> 4;
        float4 v = *(const float4*)(U + (size_t)(ntile * 64 + n) * R + rg * 4);
        Ut[rg * 4 + 0][n] = v.x;
        Ut[rg * 4 + 1][n] = v.y;
        Ut[rg * 4 + 2][n] = v.z;
        Ut[rg * 4 + 3][n] = v.w;
    }
    __syncthreads();

    unsigned long long acc[4][4];
#pragma unroll
    for (int i = 0; i < 4; i++)
#pragma unroll
        for (int j = 0; j < 4; j++) acc[i][j] = 0ULL;

#pragma unroll 16
    for (int r = 0; r < R; r++) {
        float4 u = *(float4*)&Ut[r][n0];
        float4 w = *(float4*)&Ut[r][n0 + 4];
        unsigned long long bb0 = pack2(u.x, u.y);
        unsigned long long bb1 = pack2(u.z, u.w);
        unsigned long long bb2 = pack2(w.x, w.y);
        unsigned long long bb3 = pack2(w.z, w.w);
#pragma unroll
        for (int i = 0; i < 4; i++) {
            float a = Zs[b0 + i][r];                 // broadcast (4 addrs/warp)
            unsigned long long aa = pack2(a, a);
            acc[i][0] = ffma2(aa, bb0, acc[i][0]);
            acc[i][1] = ffma2(aa, bb1, acc[i][1]);
            acc[i][2] = ffma2(aa, bb2, acc[i][2]);
            acc[i][3] = ffma2(aa, bb3, acc[i][3]);
        }
    }

    // Epilogue: coalesced 256B row segments
    const int brow = btile * 64 + b0;
    float* out = Y + (size_t)brow * NPOST + ntile * 64 + n0;
#pragma unroll
    for (int i = 0; i < 4; i++) {
        float4 o0, o1;
        unpack2(acc[i][0], o0.x, o0.y);
        unpack2(acc[i][1], o0.z, o0.w);
        unpack2(acc[i][2], o1.x, o1.y);
        unpack2(acc[i][3], o1.z, o1.w);
        *(float4*)(out + (size_t)i * NPOST)     = o0;
        *(float4*)(out + (size_t)i * NPOST + 4) = o1;
    }
}

// ===========================================================================
extern "C" void kernel_launch(void* const* d_in, const int* in_sizes, int n_in,
                              void* d_out, int out_size) {
    const float* spikes = (const float*)d_in[0];   // [512, 32768]
    const float* U      = (const float*)d_in[1];   // [32768, 64]
    const float* V      = (const float*)d_in[2];   // [32768, 64]
    float* Y            = (float*)d_out;           // [512, 32768]

    gemm1_kernel<<<dim3(KSPLIT, BATCH / A_BM), 256>>>(spikes, V);
    reduce_z_kernel<<<(BATCH * R) / 256, 256>>>();
    gemm2_kernel<<<dim3(NPOST / 64, BATCH / 64), 128>>>(U, Y);
}

// round 4
// speedup vs baseline: 3.0004x; 3.0004x over previous
#include <cuda_runtime.h>
#include <cstdint>

// y = spikes @ V @ U^T
// spikes: [512, 32768] f32   (d_in[0])
// U     : [32768, 64]  f32   (d_in[1])
// V     : [32768, 64]  f32   (d_in[2])
// mask_* inputs unused. out: [512, 32768] f32
//
// Tensor cores via portable mma.sync (sm_80+ PTX; tcgen05 is unavailable
// because the harness targets plain sm_100).  fp32 accuracy recovered with a
// bf16 hi/lo split and 3 MMA products: hi*hi + hi*lo + lo*hi  (err ~2^-18).

constexpr int BATCH = 512;
constexpr int NPRE  = 32768;
constexpr int NPOST = 32768;
constexpr int R     = 64;

constexpr int KSPLIT = 64;
constexpr int KCHUNK = NPRE / KSPLIT;   // 512

// ---------------- scratch (allocation-free: device globals) ----------------
__device__ __align__(16) float g_Zpart[KSPLIT * BATCH * R];  // 8 MB partials
__device__ __align__(16) float g_Z[BATCH * R];               // 128 KB

// ---------------- helpers ---------------------------------------------------
__device__ __forceinline__ uint32_t smem_u32(const void* p) {
    uint32_t a;
    asm("{ .reg .u64 t; cvta.to.shared.u64 t, %1; cvt.u32.u64 %0, t; }"
        : "=r"(a) : "l"(p));
    return a;
}

// round-to-nearest-even f32 -> bf16 (as uint16 in low bits)
__device__ __forceinline__ uint32_t bf16h(float x) {
    uint32_t u = __float_as_uint(x);
    return (u + 0x7FFFu + ((u >> 16) & 1u)) >> 16;
}
__device__ __forceinline__ float bf16f(uint32_t h) { return __uint_as_float(h << 16); }

// split two floats into packed bf16x2 hi and lo words (elem0 in low half)
__device__ __forceinline__ void split2(float x, float y, uint32_t& hp, uint32_t& lp) {
    uint32_t hx = bf16h(x), hy = bf16h(y);
    uint32_t lx = bf16h(x - bf16f(hx)), ly = bf16h(y - bf16f(hy));
    hp = hx | (hy << 16);
    lp = lx | (ly << 16);
}

__device__ __forceinline__ void ldm_x4(uint32_t (&r)[4], uint32_t addr) {
    asm volatile("ldmatrix.sync.aligned.m8n8.x4.shared.b16 {%0,%1,%2,%3}, [%4];"
                 : "=r"(r[0]), "=r"(r[1]), "=r"(r[2]), "=r"(r[3]) : "r"(addr));
}
__device__ __forceinline__ void ldm_x4_t(uint32_t (&r)[4], uint32_t addr) {
    asm volatile("ldmatrix.sync.aligned.m8n8.x4.trans.shared.b16 {%0,%1,%2,%3}, [%4];"
                 : "=r"(r[0]), "=r"(r[1]), "=r"(r[2]), "=r"(r[3]) : "r"(addr));
}
__device__ __forceinline__ void mma16816(float (&d)[4], const uint32_t (&a)[4],
                                         uint32_t b0, uint32_t b1) {
    asm volatile("mma.sync.aligned.m16n8k16.row.col.f32.bf16.bf16.f32 "
                 "{%0,%1,%2,%3}, {%4,%5,%6,%7}, {%8,%9}, {%0,%1,%2,%3};"
                 : "+f"(d[0]), "+f"(d[1]), "+f"(d[2]), "+f"(d[3])
                 : "r"(a[0]), "r"(a[1]), "r"(a[2]), "r"(a[3]), "r"(b0), "r"(b1));
}

// ===========================================================================
// GEMM1: Zpart[ks][b][r] = sum_{k in chunk} spikes[b][k] * V[k][r]
// Tile 128(m) x 64(n=R), K-tile 64, 8 k-tiles.  8 warps = 4m x 2n, warp 32x32.
// smem: Ah[128x64 bf16]@0 Al@16K  Bh[64k x 64n bf16, k-rows]@32K Bl@40K
// ===========================================================================
constexpr uint32_t G1_AH = 0, G1_AL = 16384, G1_BH = 32768, G1_BL = 40960;
constexpr int G1_SMEM = 49152;

__global__ void __launch_bounds__(256, 2)
g1_kernel(const float* __restrict__ S, const float* __restrict__ V) {
    extern __shared__ char sm[];
    const uint32_t sb = smem_u32(sm);
    const int tid = threadIdx.x, lane = tid & 31, w = tid >> 5;
    const int ks = blockIdx.x, mt = blockIdx.y;
    const int mbase = (w >> 1) * 32, nbase = (w & 1) * 32;

    float acc[2][4][4];
#pragma unroll
    for (int i = 0; i < 2; i++)
#pragma unroll
        for (int j = 0; j < 4; j++)
#pragma unroll
            for (int q = 0; q < 4; q++) acc[i][j][q] = 0.f;

    // staging thread map: row = (tid>>4) + 16i, seg = tid & 15 (float4 units)
    const int r0 = tid >> 4, seg = tid & 15;
    const float* Sp = S + (size_t)(mt * 128 + r0) * NPRE + ks * KCHUNK + seg * 4;
    const float* Vp = V + (size_t)(ks * KCHUNK + r0) * R + seg * 4;
    const uint32_t sxor = (uint32_t)((r0 & 7) << 4);
    uint32_t st_off[8];
#pragma unroll
    for (int i = 0; i < 8; i++)
        st_off[i] = (uint32_t)(r0 + 16 * i) * 128u + (((uint32_t)seg * 8u) ^ sxor);

    // ldmatrix lane address components
    const uint32_t lrow = (uint32_t)(lane & 15) * 128u;
    const uint32_t lhalf = (uint32_t)(lane >> 4) * 16u;
    const uint32_t lx = (uint32_t)(lane & 7) << 4;

#pragma unroll 1
    for (int kt = 0; kt < 8; kt++) {
        __syncthreads();
        const float* Sk = Sp + kt * 64;
        const float* Vk = Vp + (size_t)kt * 64 * R;
#pragma unroll
        for (int i = 0; i < 8; i++) {         // A: 128 x 64 f32
            float4 v = *(const float4*)(Sk + (size_t)i * 16 * NPRE);
            uint32_t h0, l0, h1, l1;
            split2(v.x, v.y, h0, l0);
            split2(v.z, v.w, h1, l1);
            *(uint2*)(sm + G1_AH + st_off[i]) = make_uint2(h0, h1);
            *(uint2*)(sm + G1_AL + st_off[i]) = make_uint2(l0, l1);
        }
#pragma unroll
        for (int i = 0; i < 4; i++) {         // B: 64 x 64 f32 (k-rows, direct copy)
            float4 v = *(const float4*)(Vk + (size_t)i * 16 * R);
            uint32_t h0, l0, h1, l1;
            split2(v.x, v.y, h0, l0);
            split2(v.z, v.w, h1, l1);
            *(uint2*)(sm + G1_BH + st_off[i]) = make_uint2(h0, h1);
            *(uint2*)(sm + G1_BL + st_off[i]) = make_uint2(l0, l1);
        }
        __syncthreads();

#pragma unroll
        for (int s = 0; s < 4; s++) {         // k-steps of 16
            const uint32_t c = (uint32_t)s * 32u;   // k0*2 bytes
            uint32_t ah[2][4], al[2][4];
#pragma unroll
            for (int mi = 0; mi < 2; mi++) {
                uint32_t ad = sb + G1_AH + (uint32_t)(mbase + mi * 16) * 128u
                            + lrow + ((c + lhalf) ^ lx);
                ldm_x4(ah[mi], ad);
                ldm_x4(al[mi], ad + (G1_AL - G1_AH));
            }
#pragma unroll
            for (int t = 0; t < 2; t++) {
                // trans-ldmatrix on [k][n] rows: lane k-row = s*16 + (lane&15)
                uint32_t bd = sb + G1_BH + (uint32_t)s * 16u * 128u + lrow
                            + (((uint32_t)(nbase + t * 16) * 2u + lhalf) ^ lx);
                uint32_t bh[4], bl[4];
                ldm_x4_t(bh, bd);
#pragma unroll
                for (int mi = 0; mi < 2; mi++) {
                    mma16816(acc[mi][2 * t],     ah[mi], bh[0], bh[1]);
                    mma16816(acc[mi][2 * t + 1], ah[mi], bh[2], bh[3]);
                    mma16816(acc[mi][2 * t],     al[mi], bh[0], bh[1]);
                    mma16816(acc[mi][2 * t + 1], al[mi], bh[2], bh[3]);
                }
                ldm_x4_t(bl, bd + (G1_BL - G1_BH));
#pragma unroll
                for (int mi = 0; mi < 2; mi++) {
                    mma16816(acc[mi][2 * t],     ah[mi], bl[0], bl[1]);
                    mma16816(acc[mi][2 * t + 1], ah[mi], bl[2], bl[3]);
                }
            }
        }
    }

    // epilogue -> Zpart
    float* Zb = g_Zpart + ((size_t)ks * BATCH + mt * 128) * R;
#pragma unroll
    for (int mi = 0; mi < 2; mi++)
#pragma unroll
        for (int nt = 0; nt < 4; nt++) {
            int row = mbase + mi * 16 + (lane >> 2);
            int col = nbase + nt * 8 + 2 * (lane & 3);
            *(float2*)(Zb + (size_t)row * R + col) =
                make_float2(acc[mi][nt][0], acc[mi][nt][1]);
            *(float2*)(Zb + (size_t)(row + 8) * R + col) =
                make_float2(acc[mi][nt][2], acc[mi][nt][3]);
        }
}

// ===========================================================================
// reduce: Z[i] = sum_ks Zpart[ks][i]
// ===========================================================================
__global__ void __launch_bounds__(256, 1)
reduce_z_kernel() {
    const int idx = blockIdx.x * 256 + threadIdx.x;
    float s = 0.f;
#pragma unroll
    for (int ks = 0; ks < KSPLIT; ks++)
        s += g_Zpart[(size_t)ks * (BATCH * R) + idx];
    g_Z[idx] = s;
}

// ===========================================================================
// GEMM2: Y[b][n] = sum_r Z[b][r] * U[n][r].  Tile 128(m) x 128(n), K=64.
// 8 warps = 4m x 2n, warp 32 x 64.
// smem: Zh[128x64]@0 Zl@16K  Uh[128n x 64k]@32K Ul@48K   (bf16, 128B rows)
// ===========================================================================
constexpr uint32_t G2_ZH = 0, G2_ZL = 16384, G2_UH = 32768, G2_UL = 49152;
constexpr int G2_SMEM = 65536;

__global__ void __launch_bounds__(256, 2)
g2_kernel(const float* __restrict__ U, float* __restrict__ Y) {
    extern __shared__ char sm[];
    const uint32_t sb = smem_u32(sm);
    const int tid = threadIdx.x, lane = tid & 31, w = tid >> 5;
    const int nt = blockIdx.x, mt = blockIdx.y;
    const int mbase = (w >> 1) * 32, nbase = (w & 1) * 64;

    const int r0 = tid >> 4, seg = tid & 15;
    const uint32_t sxor = (uint32_t)((r0 & 7) << 4);
    uint32_t st_off[8];
#pragma unroll
    for (int i = 0; i < 8; i++)
        st_off[i] = (uint32_t)(r0 + 16 * i) * 128u + (((uint32_t)seg * 8u) ^ sxor);

    {
        const float* Zp = g_Z + (size_t)(mt * 128 + r0) * R + seg * 4;
        const float* Up = U + (size_t)(nt * 128 + r0) * R + seg * 4;
#pragma unroll
        for (int i = 0; i < 8; i++) {
            float4 v = *(const float4*)(Zp + (size_t)i * 16 * R);
            uint32_t h0, l0, h1, l1;
            split2(v.x, v.y, h0, l0);
            split2(v.z, v.w, h1, l1);
            *(uint2*)(sm + G2_ZH + st_off[i]) = make_uint2(h0, h1);
            *(uint2*)(sm + G2_ZL + st_off[i]) = make_uint2(l0, l1);
        }
#pragma unroll
        for (int i = 0; i < 8; i++) {
            float4 v = *(const float4*)(Up + (size_t)i * 16 * R);
            uint32_t h0, l0, h1, l1;
            split2(v.x, v.y, h0, l0);
            split2(v.z, v.w, h1, l1);
            *(uint2*)(sm + G2_UH + st_off[i]) = make_uint2(h0, h1);
            *(uint2*)(sm + G2_UL + st_off[i]) = make_uint2(l0, l1);
        }
    }
    __syncthreads();

    float acc[2][8][4];
#pragma unroll
    for (int i = 0; i < 2; i++)
#pragma unroll
        for (int j = 0; j < 8; j++)
#pragma unroll
            for (int q = 0; q < 4; q++) acc[i][j][q] = 0.f;

    const uint32_t lrow = (uint32_t)(lane & 15) * 128u;
    const uint32_t lhalf = (uint32_t)(lane >> 4) * 16u;
    const uint32_t lx = (uint32_t)(lane & 7) << 4;

#pragma unroll
    for (int s = 0; s < 4; s++) {              // k-steps of 16 over K=64
        const uint32_t c = (uint32_t)s * 32u;
        uint32_t ah[2][4], al[2][4];
#pragma unroll
        for (int mi = 0; mi < 2; mi++) {
            uint32_t ad = sb + G2_ZH + (uint32_t)(mbase + mi * 16) * 128u
                        + lrow + ((c + lhalf) ^ lx);
            ldm_x4(ah[mi], ad);
            ldm_x4(al[mi], ad + (G2_ZL - G2_ZH));
        }
#pragma unroll
        for (int t = 0; t < 4; t++) {
            // non-trans ldmatrix on U [n][k] rows: lane n-row = nbase + t*16 + (lane&15)
            uint32_t bd = sb + G2_UH + (uint32_t)(nbase + t * 16) * 128u + lrow
                        + ((c + lhalf) ^ lx);
            uint32_t bh[4], bl[4];
            ldm_x4(bh, bd);
            // reg map: r0 = b0(nt 2t), r1 = b0(nt 2t+1), r2 = b1(2t), r3 = b1(2t+1)
#pragma unroll
            for (int mi = 0; mi < 2; mi++) {
                mma16816(acc[mi][2 * t],     ah[mi], bh[0], bh[2]);
                mma16816(acc[mi][2 * t + 1], ah[mi], bh[1], bh[3]);
                mma16816(acc[mi][2 * t],     al[mi], bh[0], bh[2]);
                mma16816(acc[mi][2 * t + 1], al[mi], bh[1], bh[3]);
            }
            ldm_x4(bl, bd + (G2_UL - G2_UH));
#pragma unroll
            for (int mi = 0; mi < 2; mi++) {
                mma16816(acc[mi][2 * t],     ah[mi], bl[0], bl[2]);
                mma16816(acc[mi][2 * t + 1], ah[mi], bl[1], bl[3]);
            }
        }
    }

    // epilogue -> Y
    float* Yb = Y + (size_t)(mt * 128) * NPOST + nt * 128;
#pragma unroll
    for (int mi = 0; mi < 2; mi++)
#pragma unroll
        for (int ntj = 0; ntj < 8; ntj++) {
            int row = mbase + mi * 16 + (lane >> 2);
            int col = nbase + ntj * 8 + 2 * (lane & 3);
            *(float2*)(Yb + (size_t)row * NPOST + col) =
                make_float2(acc[mi][ntj][0], acc[mi][ntj][1]);
            *(float2*)(Yb + (size_t)(row + 8) * NPOST + col) =
                make_float2(acc[mi][ntj][2], acc[mi][ntj][3]);
        }
}

// ===========================================================================
extern "C" void kernel_launch(void* const* d_in, const int* in_sizes, int n_in,
                              void* d_out, int out_size) {
    const float* spikes = (const float*)d_in[0];   // [512, 32768]
    const float* U      = (const float*)d_in[1];   // [32768, 64]
    const float* V      = (const float*)d_in[2];   // [32768, 64]
    float* Y            = (float*)d_out;           // [512, 32768]

    cudaFuncSetAttribute(g1_kernel, cudaFuncAttributeMaxDynamicSharedMemorySize, G1_SMEM);
    cudaFuncSetAttribute(g2_kernel, cudaFuncAttributeMaxDynamicSharedMemorySize, G2_SMEM);

    g1_kernel<<<dim3(KSPLIT, BATCH / 128), 256, G1_SMEM>>>(spikes, V);
    reduce_z_kernel<<<(BATCH * R) / 256, 256>>>();
    g2_kernel<<<dim3(NPOST / 128, BATCH / 128), 256, G2_SMEM>>>(U, Y);
}

// round 5
// speedup vs baseline: 3.3651x; 1.1215x over previous
#include <cuda_runtime.h>
#include <cstdint>

// y = spikes @ V @ U^T
// spikes: [512, 32768] f32   (d_in[0])
// U     : [32768, 64]  f32   (d_in[1])
// V     : [32768, 64]  f32   (d_in[2])
// mask_* inputs unused. out: [512, 32768] f32
//
// mma.sync bf16 with hi/lo split, 3 products (hi*hi + hi*lo + lo*hi).
// V, U, Z are pre-split once into packed-bf16 device buffers so the hot
// GEMMs stage them with cp.async (zero conversion work in-loop).

constexpr int BATCH = 512;
constexpr int NPRE  = 32768;
constexpr int NPOST = 32768;
constexpr int R     = 64;

constexpr int KSPLIT = 64;
constexpr int KCHUNK = NPRE / KSPLIT;   // 512

// ---------------- scratch (allocation-free: device globals) ----------------
__device__ __align__(16) float    g_Zpart[KSPLIT * BATCH * R];   // 8 MB
__device__ __align__(16) uint32_t g_Vh[NPRE * R / 2];            // 4 MB each
__device__ __align__(16) uint32_t g_Vl[NPRE * R / 2];
__device__ __align__(16) uint32_t g_Uh[NPOST * R / 2];
__device__ __align__(16) uint32_t g_Ul[NPOST * R / 2];
__device__ __align__(16) uint32_t g_Zh[BATCH * R / 2];           // 64 KB each
__device__ __align__(16) uint32_t g_Zl[BATCH * R / 2];

// ---------------- helpers ---------------------------------------------------
__device__ __forceinline__ uint32_t smem_u32(const void* p) {
    uint32_t a;
    asm("{ .reg .u64 t; cvta.to.shared.u64 t, %1; cvt.u32.u64 %0, t; }"
        : "=r"(a) : "l"(p));
    return a;
}

// cheap split: hi = round-half-up bf16 (packed via PRMT), lo = RN bf16 of
// exact residual (packed via cvt.rn.bf16x2).  elem0 in low half.
__device__ __forceinline__ void split2(float x, float y, uint32_t& hp, uint32_t& lp) {
    uint32_t vx = __float_as_uint(x) + 0x8000u;
    uint32_t vy = __float_as_uint(y) + 0x8000u;
    asm("prmt.b32 %0, %1, %2, 0x7632;" : "=r"(hp) : "r"(vx), "r"(vy));
    float lx = x - __uint_as_float(vx & 0xFFFF0000u);
    float ly = y - __uint_as_float(vy & 0xFFFF0000u);
    asm("cvt.rn.bf16x2.f32 %0, %1, %2;" : "=r"(lp) : "f"(ly), "f"(lx));
}

__device__ __forceinline__ void cp16(uint32_t dst, const void* src) {
    asm volatile("cp.async.cg.shared.global [%0], [%1], 16;"
                 :: "r"(dst), "l"(src) : "memory");
}
#define CP_COMMIT() asm volatile("cp.async.commit_group;" ::: "memory")
#define CP_WAIT0()  asm volatile("cp.async.wait_group 0;" ::: "memory")

__device__ __forceinline__ void ldm_x4(uint32_t (&r)[4], uint32_t addr) {
    asm volatile("ldmatrix.sync.aligned.m8n8.x4.shared.b16 {%0,%1,%2,%3}, [%4];"
                 : "=r"(r[0]), "=r"(r[1]), "=r"(r[2]), "=r"(r[3]) : "r"(addr));
}
__device__ __forceinline__ void ldm_x4_t(uint32_t (&r)[4], uint32_t addr) {
    asm volatile("ldmatrix.sync.aligned.m8n8.x4.trans.shared.b16 {%0,%1,%2,%3}, [%4];"
                 : "=r"(r[0]), "=r"(r[1]), "=r"(r[2]), "=r"(r[3]) : "r"(addr));
}
__device__ __forceinline__ void mma16816(float (&d)[4], const uint32_t (&a)[4],
                                         uint32_t b0, uint32_t b1) {
    asm volatile("mma.sync.aligned.m16n8k16.row.col.f32.bf16.bf16.f32 "
                 "{%0,%1,%2,%3}, {%4,%5,%6,%7}, {%8,%9}, {%0,%1,%2,%3};"
                 : "+f"(d[0]), "+f"(d[1]), "+f"(d[2]), "+f"(d[3])
                 : "r"(a[0]), "r"(a[1]), "r"(a[2]), "r"(a[3]), "r"(b0), "r"(b1));
}

// ===========================================================================
// prep: split V and U into packed bf16 hi/lo buffers
// ===========================================================================
__global__ void __launch_bounds__(256, 4)
split_vu_kernel(const float* __restrict__ V, const float* __restrict__ U) {
    const int gid = blockIdx.x * 256 + threadIdx.x;       // float4 index
    const float4* src = (blockIdx.y == 0) ? (const float4*)V : (const float4*)U;
    uint2* dh = (blockIdx.y == 0) ? (uint2*)g_Vh : (uint2*)g_Uh;
    uint2* dl = (blockIdx.y == 0) ? (uint2*)g_Vl : (uint2*)g_Ul;
    float4 v = src[gid];
    uint32_t h0, l0, h1, l1;
    split2(v.x, v.y, h0, l0);
    split2(v.z, v.w, h1, l1);
    dh[gid] = make_uint2(h0, h1);
    dl[gid] = make_uint2(l0, l1);
}

// ===========================================================================
// GEMM1: Zpart[ks][b][r] = sum_{k in chunk} spikes[b][k] * V[k][r]
// Tile 128(m) x 64(n=R), K-tile 64, 8 k-tiles, double-buffered smem.
// 8 warps = 4m x 2n, warp 32x32.
// per-buffer smem: Ah[128x64 bf16]@0 Al@16K  Bh[64k x 64n]@32K Bl@40K (48K)
// ===========================================================================
constexpr uint32_t G1_AL = 16384, G1_BH = 32768, G1_BL = 40960;
constexpr uint32_t G1_BUF = 49152;
constexpr int G1_SMEM = 98304;

__global__ void __launch_bounds__(256, 2)
g1_kernel(const float* __restrict__ S) {
    extern __shared__ char sm[];
    const uint32_t sb = smem_u32(sm);
    const int tid = threadIdx.x, lane = tid & 31, w = tid >> 5;
    const int ks = blockIdx.x, mt = blockIdx.y;
    const int mbase = (w >> 1) * 32, nbase = (w & 1) * 32;
    const int kbase = ks * KCHUNK;

    float acc[2][4][4];
#pragma unroll
    for (int i = 0; i < 2; i++)
#pragma unroll
        for (int j = 0; j < 4; j++)
#pragma unroll
            for (int q = 0; q < 4; q++) acc[i][j][q] = 0.f;

    // A staging map: row = (tid>>4) + 16i, seg = tid & 15 (float4 units)
    const int r0 = tid >> 4, seg = tid & 15;
    const float* Sp = S + (size_t)(mt * 128 + r0) * NPRE + kbase + seg * 4;
    const uint32_t sxor = (uint32_t)((r0 & 7) << 4);
    uint32_t a_off[8];
#pragma unroll
    for (int i = 0; i < 8; i++)
        a_off[i] = (uint32_t)(r0 + 16 * i) * 128u + (((uint32_t)seg * 8u) ^ sxor);

    // B cp.async map: 2 chunks of 16B per half per thread
    uint32_t b_dst[2];
    uint32_t b_row[2];
#pragma unroll
    for (int i = 0; i < 2; i++) {
        uint32_t ch = (uint32_t)tid + 256u * i;   // 0..511
        uint32_t row = ch >> 3, sg = ch & 7;
        b_row[i] = row * 128u + sg * 16u;         // byte offset in gmem row-major
        b_dst[i] = row * 128u + ((sg * 16u) ^ ((row & 7u) << 4));
    }

    // ldmatrix lane address components
    const uint32_t lrow  = (uint32_t)(lane & 15) * 128u;
    const uint32_t lhalf = (uint32_t)(lane >> 4) * 16u;
    const uint32_t lx    = (uint32_t)(lane & 7) << 4;

    // prologue: issue B(0) into buf0; prefetch A(0) regs
    {
        const char* vh = (const char*)g_Vh + (size_t)kbase * 128;
        const char* vl = (const char*)g_Vl + (size_t)kbase * 128;
#pragma unroll
        for (int i = 0; i < 2; i++) {
            cp16(sb + G1_BH + b_dst[i], vh + b_row[i]);
            cp16(sb + G1_BL + b_dst[i], vl + b_row[i]);
        }
        CP_COMMIT();
    }
    float4 ra[8];
#pragma unroll
    for (int i = 0; i < 8; i++) ra[i] = *(const float4*)(Sp + (size_t)i * 16 * NPRE);

#pragma unroll 1
    for (int kt = 0; kt < 8; kt++) {
        const uint32_t cur = (uint32_t)(kt & 1);
        const uint32_t bufb = sb + cur * G1_BUF;
        char* bufc = sm + cur * G1_BUF;

        // store A(kt) hi/lo into buf cur
#pragma unroll
        for (int i = 0; i < 8; i++) {
            uint32_t h0, l0, h1, l1;
            split2(ra[i].x, ra[i].y, h0, l0);
            split2(ra[i].z, ra[i].w, h1, l1);
            *(uint2*)(bufc + a_off[i])         = make_uint2(h0, h1);
            *(uint2*)(bufc + G1_AL + a_off[i]) = make_uint2(l0, l1);
        }
        CP_WAIT0();          // B(kt) (issued last iter) complete
        __syncthreads();     // A(kt)+B(kt) visible; mma(kt-1) reads done

        // issue B(kt+1) into the other buffer; prefetch A(kt+1) regs
        if (kt + 1 < 8) {
            const char* vh = (const char*)g_Vh + ((size_t)kbase + (kt + 1) * 64) * 128;
            const char* vl = (const char*)g_Vl + ((size_t)kbase + (kt + 1) * 64) * 128;
            const uint32_t obb = sb + (cur ^ 1u) * G1_BUF;
#pragma unroll
            for (int i = 0; i < 2; i++) {
                cp16(obb + G1_BH + b_dst[i], vh + b_row[i]);
                cp16(obb + G1_BL + b_dst[i], vl + b_row[i]);
            }
            CP_COMMIT();
            const float* Sk = Sp + (kt + 1) * 64;
#pragma unroll
            for (int i = 0; i < 8; i++) ra[i] = *(const float4*)(Sk + (size_t)i * 16 * NPRE);
        }

        // mma on buf cur
#pragma unroll
        for (int s = 0; s < 4; s++) {
            const uint32_t c = (uint32_t)s * 32u;
            uint32_t ah[2][4], al[2][4];
#pragma unroll
            for (int mi = 0; mi < 2; mi++) {
                uint32_t ad = bufb + (uint32_t)(mbase + mi * 16) * 128u
                            + lrow + ((c + lhalf) ^ lx);
                ldm_x4(ah[mi], ad);
                ldm_x4(al[mi], ad + G1_AL);
            }
#pragma unroll
            for (int t = 0; t < 2; t++) {
                uint32_t bd = bufb + G1_BH + (uint32_t)s * 16u * 128u + lrow
                            + (((uint32_t)(nbase + t * 16) * 2u + lhalf) ^ lx);
                uint32_t bh[4], bl[4];
                ldm_x4_t(bh, bd);
#pragma unroll
                for (int mi = 0; mi < 2; mi++) {
                    mma16816(acc[mi][2 * t],     ah[mi], bh[0], bh[1]);
                    mma16816(acc[mi][2 * t + 1], ah[mi], bh[2], bh[3]);
                    mma16816(acc[mi][2 * t],     al[mi], bh[0], bh[1]);
                    mma16816(acc[mi][2 * t + 1], al[mi], bh[2], bh[3]);
                }
                ldm_x4_t(bl, bd + (G1_BL - G1_BH));
#pragma unroll
                for (int mi = 0; mi < 2; mi++) {
                    mma16816(acc[mi][2 * t],     ah[mi], bl[0], bl[1]);
                    mma16816(acc[mi][2 * t + 1], ah[mi], bl[2], bl[3]);
                }
            }
        }
    }

    // epilogue -> Zpart
    float* Zb = g_Zpart + ((size_t)ks * BATCH + mt * 128) * R;
#pragma unroll
    for (int mi = 0; mi < 2; mi++)
#pragma unroll
        for (int nt = 0; nt < 4; nt++) {
            int row = mbase + mi * 16 + (lane >> 2);
            int col = nbase + nt * 8 + 2 * (lane & 3);
            *(float2*)(Zb + (size_t)row * R + col) =
                make_float2(acc[mi][nt][0], acc[mi][nt][1]);
            *(float2*)(Zb + (size_t)(row + 8) * R + col) =
                make_float2(acc[mi][nt][2], acc[mi][nt][3]);
        }
}

// ===========================================================================
// reduce + split: Z = sum_ks Zpart; write packed bf16 hi/lo
// ===========================================================================
__global__ void __launch_bounds__(256, 4)
reduce_split_kernel() {
    const int gid = blockIdx.x * 256 + threadIdx.x;       // pair index, 0..16383
    const float2* p = (const float2*)g_Zpart;
    float sx = 0.f, sy = 0.f;
#pragma unroll
    for (int ks = 0; ks < KSPLIT; ks++) {
        float2 v = p[(size_t)ks * (BATCH * R / 2) + gid];
        sx += v.x;
        sy += v.y;
    }
    uint32_t h, l;
    split2(sx, sy, h, l);
    g_Zh[gid] = h;
    g_Zl[gid] = l;
}

// ===========================================================================
// GEMM2: Y[b][n] = sum_r Z[b][r] * U[n][r].  Tile 128(m) x 128(n), K=64.
// All operands pre-split bf16, staged via cp.async.  8 warps = 4m x 2n.
// smem: Zh@0 Zl@16K Uh@32K Ul@48K  (each 128 rows x 128B)
// ===========================================================================
constexpr uint32_t G2_ZL = 16384, G2_UH = 32768, G2_UL = 49152;
constexpr int G2_SMEM = 65536;

__global__ void __launch_bounds__(256, 2)
g2_kernel(float* __restrict__ Y) {
    extern __shared__ char sm[];
    const uint32_t sb = smem_u32(sm);
    const int tid = threadIdx.x, lane = tid & 31, w = tid >> 5;
    const int nt = blockIdx.x, mt = blockIdx.y;
    const int mbase = (w >> 1) * 32, nbase = (w & 1) * 64;

    // stage Z and U tiles: 4 regions x 16KB; 4 chunks of 16B per region per thread
    {
        const char* zh = (const char*)g_Zh + (size_t)mt * 128 * 128;
        const char* zl = (const char*)g_Zl + (size_t)mt * 128 * 128;
        const char* uh = (const char*)g_Uh + (size_t)nt * 128 * 128;
        const char* ul = (const char*)g_Ul + (size_t)nt * 128 * 128;
#pragma unroll
        for (int i = 0; i < 4; i++) {
            uint32_t ch = (uint32_t)tid + 256u * i;  // 0..1023
            uint32_t row = ch >> 3, sg = ch & 7;
            uint32_t so = row * 128u + sg * 16u;
            uint32_t dof = row * 128u + ((sg * 16u) ^ ((row & 7u) << 4));
            cp16(sb + dof,         zh + so);
            cp16(sb + G2_ZL + dof, zl + so);
            cp16(sb + G2_UH + dof, uh + so);
            cp16(sb + G2_UL + dof, ul + so);
        }
        CP_COMMIT();
    }

    float acc[2][8][4];
#pragma unroll
    for (int i = 0; i < 2; i++)
#pragma unroll
        for (int j = 0; j < 8; j++)
#pragma unroll
            for (int q = 0; q < 4; q++) acc[i][j][q] = 0.f;

    const uint32_t lrow  = (uint32_t)(lane & 15) * 128u;
    const uint32_t lhalf = (uint32_t)(lane >> 4) * 16u;
    const uint32_t lx    = (uint32_t)(lane & 7) << 4;

    CP_WAIT0();
    __syncthreads();

#pragma unroll
    for (int s = 0; s < 4; s++) {              // k-steps of 16 over K=64
        const uint32_t c = (uint32_t)s * 32u;
        uint32_t ah[2][4], al[2][4];
#pragma unroll
        for (int mi = 0; mi < 2; mi++) {
            uint32_t ad = sb + (uint32_t)(mbase + mi * 16) * 128u
                        + lrow + ((c + lhalf) ^ lx);
            ldm_x4(ah[mi], ad);
            ldm_x4(al[mi], ad + G2_ZL);
        }
#pragma unroll
        for (int t = 0; t < 4; t++) {
            uint32_t bd = sb + G2_UH + (uint32_t)(nbase + t * 16) * 128u + lrow
                        + ((c + lhalf) ^ lx);
            uint32_t bh[4], bl[4];
            ldm_x4(bh, bd);
#pragma unroll
            for (int mi = 0; mi < 2; mi++) {
                mma16816(acc[mi][2 * t],     ah[mi], bh[0], bh[2]);
                mma16816(acc[mi][2 * t + 1], ah[mi], bh[1], bh[3]);
                mma16816(acc[mi][2 * t],     al[mi], bh[0], bh[2]);
                mma16816(acc[mi][2 * t + 1], al[mi], bh[1], bh[3]);
            }
            ldm_x4(bl, bd + (G2_UL - G2_UH));
#pragma unroll
            for (int mi = 0; mi < 2; mi++) {
                mma16816(acc[mi][2 * t],     ah[mi], bl[0], bl[2]);
                mma16816(acc[mi][2 * t + 1], ah[mi], bl[1], bl[3]);
            }
        }
    }

    // epilogue -> Y
    float* Yb = Y + (size_t)(mt * 128) * NPOST + nt * 128;
#pragma unroll
    for (int mi = 0; mi < 2; mi++)
#pragma unroll
        for (int ntj = 0; ntj < 8; ntj++) {
            int row = mbase + mi * 16 + (lane >> 2);
            int col = nbase + ntj * 8 + 2 * (lane & 3);
            *(float2*)(Yb + (size_t)row * NPOST + col) =
                make_float2(acc[mi][ntj][0], acc[mi][ntj][1]);
            *(float2*)(Yb + (size_t)(row + 8) * NPOST + col) =
                make_float2(acc[mi][ntj][2], acc[mi][ntj][3]);
        }
}

// ===========================================================================
extern "C" void kernel_launch(void* const* d_in, const int* in_sizes, int n_in,
                              void* d_out, int out_size) {
    const float* spikes = (const float*)d_in[0];   // [512, 32768]
    const float* U      = (const float*)d_in[1];   // [32768, 64]
    const float* V      = (const float*)d_in[2];   // [32768, 64]
    float* Y            = (float*)d_out;           // [512, 32768]

    cudaFuncSetAttribute(g1_kernel, cudaFuncAttributeMaxDynamicSharedMemorySize, G1_SMEM);
    cudaFuncSetAttribute(g2_kernel, cudaFuncAttributeMaxDynamicSharedMemorySize, G2_SMEM);

    split_vu_kernel<<<dim3(NPRE * R / 4 / 256, 2), 256>>>(V, U);
    g1_kernel<<<dim3(KSPLIT, BATCH / 128), 256, G1_SMEM>>>(spikes);
    reduce_split_kernel<<<(BATCH * R / 2) / 256, 256>>>();
    g2_kernel<<<dim3(NPOST / 128, BATCH / 128), 256, G2_SMEM>>>(Y);
}